// round 1
// baseline (speedup 1.0000x reference)
#include <cuda_runtime.h>
#include <cuda_bf16.h>
#include <cstdint>

// ---------------- problem constants ----------------
#define NN      100000      // nodes per type
#define EE      250000      // edges per relation
#define HH      4           // heads
#define CC      32          // channels per head
#define HD      128         // H*C
#define DIN     128
#define NOUT    349

// ---------------- device scratch (no allocs allowed) ----------------
__device__ float g_H1 [NN * HD];   // h_s for current relation
__device__ float g_XP1[NN * HD];   // layer0 paper accumulator -> layer1 paper input
__device__ float g_XA1[NN * HD];   // layer0 author accumulator -> layer1 author input
__device__ float g_XP2[NN * HD];   // layer1 paper accumulator
__device__ float g_AS [NN * HH];   // a_src for current relation
__device__ float g_AD [NN * HH];   // a_dst for current relation
__device__ float g_Z  [NN * HH];   // softmax denominators
__device__ float g_EW [EE * HH];   // per-edge exp weights
__device__ float g_VS [DIN * HH];  // projected att_src vector
__device__ float g_VD [DIN * HH];  // projected att_dst vector

// ---------------- kernels ----------------

// v[k][h] = sum_c W[k][h*32+c] * att[h][c]   (128 threads)
__global__ void prep_v_kernel(const float* __restrict__ W,
                              const float* __restrict__ att,
                              float* __restrict__ v)
{
    int k = threadIdx.x;
    if (k >= DIN) return;
    #pragma unroll
    for (int h = 0; h < HH; h++) {
        float s = 0.f;
        #pragma unroll
        for (int c = 0; c < CC; c++)
            s += W[k * HD + h * CC + c] * att[h * CC + c];
        v[k * HH + h] = s;
    }
}

// out[n][h] = sum_k x[n][k] * v[k][h]   (warp per node, grid-stride)
__global__ void proj_kernel(const float* __restrict__ x,
                            const float* __restrict__ v,
                            float* __restrict__ out, int n)
{
    int lane   = threadIdx.x & 31;
    int warp   = (blockIdx.x * blockDim.x + threadIdx.x) >> 5;
    int nwarps = (gridDim.x * blockDim.x) >> 5;

    const float4* v4 = reinterpret_cast<const float4*>(v);
    float4 v0 = v4[lane * 4 + 0];
    float4 v1 = v4[lane * 4 + 1];
    float4 v2 = v4[lane * 4 + 2];
    float4 v3 = v4[lane * 4 + 3];

    const float4* x4 = reinterpret_cast<const float4*>(x);
    for (int node = warp; node < n; node += nwarps) {
        float4 xv = x4[(size_t)node * 32 + lane];
        float4 a;
        a.x = xv.x * v0.x + xv.y * v1.x + xv.z * v2.x + xv.w * v3.x;
        a.y = xv.x * v0.y + xv.y * v1.y + xv.z * v2.y + xv.w * v3.y;
        a.z = xv.x * v0.z + xv.y * v1.z + xv.z * v2.z + xv.w * v3.z;
        a.w = xv.x * v0.w + xv.y * v1.w + xv.z * v2.w + xv.w * v3.w;
        #pragma unroll
        for (int off = 16; off; off >>= 1) {
            a.x += __shfl_xor_sync(0xffffffff, a.x, off);
            a.y += __shfl_xor_sync(0xffffffff, a.y, off);
            a.z += __shfl_xor_sync(0xffffffff, a.z, off);
            a.w += __shfl_xor_sync(0xffffffff, a.w, off);
        }
        if (lane == 0)
            reinterpret_cast<float4*>(out)[node] = a;
    }
}

// per-edge: w = exp(leaky(a_s[src]+a_d[dst],0.2)); store w; Z[dst] += w
__global__ void edge_logits_kernel(const int* __restrict__ ei,
                                   const float* __restrict__ AS,
                                   const float* __restrict__ AD,
                                   float* __restrict__ EW,
                                   float* __restrict__ Z, int E)
{
    int e = blockIdx.x * blockDim.x + threadIdx.x;
    if (e >= E) return;
    int src = ei[e];
    int dst = ei[E + e];
    float4 s = reinterpret_cast<const float4*>(AS)[src];
    float4 d = reinterpret_cast<const float4*>(AD)[dst];
    float4 w;
    float t;
    t = s.x + d.x; t = fmaxf(t, 0.2f * t); w.x = expf(t);
    t = s.y + d.y; t = fmaxf(t, 0.2f * t); w.y = expf(t);
    t = s.z + d.z; t = fmaxf(t, 0.2f * t); w.z = expf(t);
    t = s.w + d.w; t = fmaxf(t, 0.2f * t); w.w = expf(t);
    reinterpret_cast<float4*>(EW)[e] = w;
    atomicAdd(reinterpret_cast<float4*>(Z + (size_t)dst * HH), w);
}

// warp per edge: acc[dst] += h_s[src] * alpha    (lane handles 4 channels)
__global__ void edge_scatter_kernel(const int* __restrict__ ei,
                                    const float* __restrict__ hsrc,
                                    const float* __restrict__ Z,
                                    const float* __restrict__ EW,
                                    float* __restrict__ acc, int E)
{
    int e    = (blockIdx.x * blockDim.x + threadIdx.x) >> 5;
    int lane = threadIdx.x & 31;
    if (e >= E) return;
    int src = ei[e];
    int dst = ei[E + e];
    int h   = lane >> 3;                   // 4 channels per lane -> head = lane/8
    float w = EW[(size_t)e * HH + h];
    float z = Z[(size_t)dst * HH + h];
    float alpha = w / (z + 1e-16f);
    float4 hv = *reinterpret_cast<const float4*>(hsrc + (size_t)src * HD + lane * 4);
    float4 m  = make_float4(hv.x * alpha, hv.y * alpha, hv.z * alpha, hv.w * alpha);
    atomicAdd(reinterpret_cast<float4*>(acc + (size_t)dst * HD + lane * 4), m);
}

// y = maybe_leaky(y + b1 [+ b2])
__global__ void bias_act_kernel(float* __restrict__ y,
                                const float* __restrict__ b1,
                                const float* __restrict__ b2,
                                int total, float slope, int do_act)
{
    int i = blockIdx.x * blockDim.x + threadIdx.x;
    if (i >= total) return;
    int j = i & (HD - 1);
    float v = y[i] + b1[j];
    if (b2) v += b2[j];
    if (do_act) v = fmaxf(v, slope * v);
    y[i] = v;
}

// C[M,Nc] = A[M,128] @ B[128,Nc] (+bias). 128x128 block tile, 8x8 per thread.
template <bool ALIGN4>
__global__ void gemm_kernel(const float* __restrict__ A,
                            const float* __restrict__ B,
                            float* __restrict__ C,
                            int M, int Nc,
                            const float* __restrict__ bias)
{
    const int K = 128;
    __shared__ float As[16][128];   // [k][m]
    __shared__ float Bs[16][128];   // [k][n]

    int m0  = blockIdx.x * 128;
    int n0  = blockIdx.y * 128;
    int tid = threadIdx.x;          // 256
    int tx  = tid & 15;
    int ty  = tid >> 4;

    float acc[8][8];
    #pragma unroll
    for (int i = 0; i < 8; i++)
        #pragma unroll
        for (int j = 0; j < 8; j++) acc[i][j] = 0.f;

    for (int k0 = 0; k0 < K; k0 += 16) {
        // load A tile (128 rows x 16 k), 2 float4 per thread, transposed into As[k][m]
        #pragma unroll
        for (int i = 0; i < 2; i++) {
            int idx = tid * 2 + i;          // 0..511
            int row = idx >> 2;
            int kq  = idx & 3;
            float4 v = make_float4(0.f, 0.f, 0.f, 0.f);
            int gm = m0 + row;
            if (gm < M)
                v = *reinterpret_cast<const float4*>(A + (size_t)gm * K + k0 + kq * 4);
            As[kq * 4 + 0][row] = v.x;
            As[kq * 4 + 1][row] = v.y;
            As[kq * 4 + 2][row] = v.z;
            As[kq * 4 + 3][row] = v.w;
        }
        // load B tile (16 k-rows x 128 cols)
        #pragma unroll
        for (int i = 0; i < 2; i++) {
            int idx  = tid * 2 + i;
            int krow = idx >> 5;            // 0..15
            int colq = idx & 31;
            int gn   = n0 + colq * 4;
            if (ALIGN4) {
                float4 v = make_float4(0.f, 0.f, 0.f, 0.f);
                if (gn < Nc)
                    v = *reinterpret_cast<const float4*>(B + (size_t)(k0 + krow) * Nc + gn);
                *reinterpret_cast<float4*>(&Bs[krow][colq * 4]) = v;
            } else {
                #pragma unroll
                for (int j = 0; j < 4; j++) {
                    float v = 0.f;
                    if (gn + j < Nc)
                        v = B[(size_t)(k0 + krow) * Nc + gn + j];
                    Bs[krow][colq * 4 + j] = v;
                }
            }
        }
        __syncthreads();

        #pragma unroll
        for (int kk = 0; kk < 16; kk++) {
            float a[8], b[8];
            *reinterpret_cast<float4*>(&a[0]) = *reinterpret_cast<float4*>(&As[kk][ty * 8]);
            *reinterpret_cast<float4*>(&a[4]) = *reinterpret_cast<float4*>(&As[kk][ty * 8 + 4]);
            *reinterpret_cast<float4*>(&b[0]) = *reinterpret_cast<float4*>(&Bs[kk][tx * 8]);
            *reinterpret_cast<float4*>(&b[4]) = *reinterpret_cast<float4*>(&Bs[kk][tx * 8 + 4]);
            #pragma unroll
            for (int i = 0; i < 8; i++)
                #pragma unroll
                for (int j = 0; j < 8; j++)
                    acc[i][j] += a[i] * b[j];
        }
        __syncthreads();
    }

    #pragma unroll
    for (int i = 0; i < 8; i++) {
        int gm = m0 + ty * 8 + i;
        if (gm >= M) continue;
        #pragma unroll
        for (int j = 0; j < 8; j++) {
            int gn = n0 + tx * 8 + j;
            if (gn < Nc) {
                float v = acc[i][j];
                if (bias) v += bias[gn];
                C[(size_t)gm * Nc + gn] = v;
            }
        }
    }
}

// ---------------- host launch ----------------
extern "C" void kernel_launch(void* const* d_in, const int* in_sizes, int n_in,
                              void* d_out, int out_size)
{
    // Classify inputs by unique element counts (robust to metadata ordering).
    const float* xs[2]   = {nullptr, nullptr}; int nx = 0;   // x_paper, x_author
    const int*   eis[3]  = {nullptr, nullptr, nullptr}; int ne = 0; // cites, writes, written
    const float* Ws[6]   = {}; int nw = 0;                   // W0_c W0_w W0_wb W1_c W1_w W1_wb
    const float* attb[18]= {}; int na = 0;                   // (as, ad, b) x 6 rel-layers
    const float* linW = nullptr;
    const float* linb = nullptr;

    for (int i = 0; i < n_in; i++) {
        int s = in_sizes[i];
        if      (s == NN * DIN   && nx < 2)  xs[nx++]   = (const float*)d_in[i];
        else if (s == 2 * EE     && ne < 3)  eis[ne++]  = (const int*)d_in[i];
        else if (s == DIN * HD   && nw < 6)  Ws[nw++]   = (const float*)d_in[i];
        else if (s == HD         && na < 18) attb[na++] = (const float*)d_in[i];
        else if (s == HD * NOUT)             linW       = (const float*)d_in[i];
        else if (s == NOUT)                  linb       = (const float*)d_in[i];
    }
    if (nx != 2 || ne != 3 || nw != 6 || na != 18 || !linW || !linb) return;

    float *pH1, *pXP1, *pXA1, *pXP2, *pAS, *pAD, *pZ, *pEW, *pVS, *pVD;
    cudaGetSymbolAddress((void**)&pH1,  g_H1);
    cudaGetSymbolAddress((void**)&pXP1, g_XP1);
    cudaGetSymbolAddress((void**)&pXA1, g_XA1);
    cudaGetSymbolAddress((void**)&pXP2, g_XP2);
    cudaGetSymbolAddress((void**)&pAS,  g_AS);
    cudaGetSymbolAddress((void**)&pAD,  g_AD);
    cudaGetSymbolAddress((void**)&pZ,   g_Z);
    cudaGetSymbolAddress((void**)&pEW,  g_EW);
    cudaGetSymbolAddress((void**)&pVS,  g_VS);
    cudaGetSymbolAddress((void**)&pVD,  g_VD);

    const size_t featBytes = (size_t)NN * HD * sizeof(float);

    auto relation = [&](const float* xsrc, const float* xdst, const int* ei,
                        const float* W, const float* att_s, const float* att_d,
                        float* acc)
    {
        prep_v_kernel<<<1, 128>>>(W, att_s, pVS);
        prep_v_kernel<<<1, 128>>>(W, att_d, pVD);
        proj_kernel<<<512, 256>>>(xsrc, pVS, pAS, NN);
        proj_kernel<<<512, 256>>>(xdst, pVD, pAD, NN);
        cudaMemsetAsync(pZ, 0, (size_t)NN * HH * sizeof(float));
        gemm_kernel<true><<<dim3((NN + 127) / 128, 1), 256>>>(xsrc, W, pH1, NN, HD, nullptr);
        edge_logits_kernel<<<(EE + 255) / 256, 256>>>(ei, pAS, pAD, pEW, pZ, EE);
        edge_scatter_kernel<<<(EE + 7) / 8, 256>>>(ei, pH1, pZ, pEW, acc, EE);
    };

    // ---- layer 0 ----
    cudaMemsetAsync(pXP1, 0, featBytes);
    cudaMemsetAsync(pXA1, 0, featBytes);
    // cites: paper -> paper   (W0_c = Ws[0], as0_c ad0_c b0_c = attb[0..2])
    relation(xs[0], xs[0], eis[0], Ws[0], attb[0], attb[1], pXP1);
    // writes: author -> paper (W0_w = Ws[1], attb[3..5])
    relation(xs[1], xs[0], eis[1], Ws[1], attb[3], attb[4], pXP1);
    // written_by: paper -> author (W0_wb = Ws[2], attb[6..8])
    relation(xs[0], xs[1], eis[2], Ws[2], attb[6], attb[7], pXA1);

    int total = NN * HD;
    bias_act_kernel<<<(total + 255) / 256, 256>>>(pXP1, attb[2], attb[5], total, 0.01f, 1);
    bias_act_kernel<<<(total + 255) / 256, 256>>>(pXA1, attb[8], nullptr, total, 0.01f, 1);

    // ---- layer 1 (author output is dead: only paper feeds the classifier) ----
    cudaMemsetAsync(pXP2, 0, featBytes);
    relation(pXP1, pXP1, eis[0], Ws[3], attb[9],  attb[10], pXP2);  // cites, W1_c
    relation(pXA1, pXP1, eis[1], Ws[4], attb[12], attb[13], pXP2);  // writes, W1_w
    bias_act_kernel<<<(total + 255) / 256, 256>>>(pXP2, attb[11], attb[14], total, 0.f, 0);

    // ---- classifier: out[N,349] = xp2 @ lin_W + lin_b ----
    gemm_kernel<false><<<dim3((NN + 127) / 128, (NOUT + 127) / 128), 256>>>(
        pXP2, linW, (float*)d_out, NN, NOUT, linb);
}

// round 3
// speedup vs baseline: 1.1553x; 1.1553x over previous
#include <cuda_runtime.h>
#include <cuda_bf16.h>
#include <cstdint>

// ---------------- problem constants ----------------
#define NN      100000      // nodes per type
#define EE      250000      // edges per relation
#define HH      4           // heads
#define CC      32          // channels per head
#define HD      128         // H*C
#define DIN     128
#define NOUT    349

// ---------------- device scratch (no allocs allowed) ----------------
__device__ float g_H1 [NN * HD];       // h_s for current relation
__device__ float g_XP1[NN * HD];       // layer0 paper accumulator
__device__ float g_XA1[NN * HD];       // layer0 author accumulator
__device__ float g_XP2[NN * HD];       // layer1 paper accumulator
__device__ float g_P  [6 * NN * HH];   // projections: AS_c, AD_c, AD_w, AS_wb, AS_w, AD_wb
__device__ float g_Z  [3 * NN * HH];   // softmax denominators (one per relation)
__device__ float g_EW [EE * HH];       // per-edge exp weights
__device__ float g_V  [6 * DIN * HH];  // projected attention vectors (6 slots x 512)

// ---------------- small kernels ----------------

// v[k][h] = sum_c W[k][h*32+c] * att[h][c]
__global__ void prep_v_kernel(const float* __restrict__ W,
                              const float* __restrict__ att,
                              float* __restrict__ v)
{
    int k = threadIdx.x;
    if (k >= DIN) return;
    #pragma unroll
    for (int h = 0; h < HH; h++) {
        float s = 0.f;
        #pragma unroll
        for (int c = 0; c < CC; c++)
            s += W[k * HD + h * CC + c] * att[h * CC + c];
        v[k * HH + h] = s;
    }
}

// NV projections in a single pass over x. out[v][n][h] = sum_k x[n][k] * V[v][k][h]
template <int NV>
__global__ void __launch_bounds__(256) proj_multi_kernel(
    const float* __restrict__ x, const float* __restrict__ V,
    float* __restrict__ o0, float* __restrict__ o1,
    float* __restrict__ o2, float* __restrict__ o3, int n)
{
    int lane   = threadIdx.x & 31;
    int warp   = (blockIdx.x * blockDim.x + threadIdx.x) >> 5;
    int nwarps = (gridDim.x * blockDim.x) >> 5;

    const float4* V4 = reinterpret_cast<const float4*>(V);
    float4 vv[NV][4];
    #pragma unroll
    for (int v = 0; v < NV; v++)
        #pragma unroll
        for (int q = 0; q < 4; q++)
            vv[v][q] = V4[v * 128 + lane * 4 + q];

    float* outs[4] = {o0, o1, o2, o3};
    const float4* x4 = reinterpret_cast<const float4*>(x);

    for (int node = warp; node < n; node += nwarps) {
        float4 xv = x4[(size_t)node * 32 + lane];
        float4 a[NV];
        #pragma unroll
        for (int v = 0; v < NV; v++) {
            a[v].x = xv.x * vv[v][0].x + xv.y * vv[v][1].x + xv.z * vv[v][2].x + xv.w * vv[v][3].x;
            a[v].y = xv.x * vv[v][0].y + xv.y * vv[v][1].y + xv.z * vv[v][2].y + xv.w * vv[v][3].y;
            a[v].z = xv.x * vv[v][0].z + xv.y * vv[v][1].z + xv.z * vv[v][2].z + xv.w * vv[v][3].z;
            a[v].w = xv.x * vv[v][0].w + xv.y * vv[v][1].w + xv.z * vv[v][2].w + xv.w * vv[v][3].w;
        }
        #pragma unroll
        for (int off = 16; off; off >>= 1) {
            #pragma unroll
            for (int v = 0; v < NV; v++) {
                a[v].x += __shfl_xor_sync(0xffffffff, a[v].x, off);
                a[v].y += __shfl_xor_sync(0xffffffff, a[v].y, off);
                a[v].z += __shfl_xor_sync(0xffffffff, a[v].z, off);
                a[v].w += __shfl_xor_sync(0xffffffff, a[v].w, off);
            }
        }
        if (lane == 0) {
            #pragma unroll
            for (int v = 0; v < NV; v++)
                reinterpret_cast<float4*>(outs[v])[node] = a[v];
        }
    }
}

// per-edge: w = exp(leaky(a_s[src]+a_d[dst],0.2)); store w; Z[dst] += w
__global__ void edge_logits_kernel(const int* __restrict__ ei,
                                   const float* __restrict__ AS,
                                   const float* __restrict__ AD,
                                   float* __restrict__ EW,
                                   float* __restrict__ Z, int E)
{
    int e = blockIdx.x * blockDim.x + threadIdx.x;
    if (e >= E) return;
    int src = ei[e];
    int dst = ei[E + e];
    float4 s = reinterpret_cast<const float4*>(AS)[src];
    float4 d = reinterpret_cast<const float4*>(AD)[dst];
    float4 w;
    float t;
    t = s.x + d.x; t = fmaxf(t, 0.2f * t); w.x = expf(t);
    t = s.y + d.y; t = fmaxf(t, 0.2f * t); w.y = expf(t);
    t = s.z + d.z; t = fmaxf(t, 0.2f * t); w.z = expf(t);
    t = s.w + d.w; t = fmaxf(t, 0.2f * t); w.w = expf(t);
    reinterpret_cast<float4*>(EW)[e] = w;
    atomicAdd(reinterpret_cast<float4*>(Z + (size_t)dst * HH), w);
}

// warp per edge: acc[dst] += h_s[src] * alpha  (lane handles 4 channels)
__global__ void edge_scatter_kernel(const int* __restrict__ ei,
                                    const float* __restrict__ hsrc,
                                    const float* __restrict__ Z,
                                    const float* __restrict__ EW,
                                    float* __restrict__ acc, int E)
{
    int e    = (blockIdx.x * blockDim.x + threadIdx.x) >> 5;
    int lane = threadIdx.x & 31;
    if (e >= E) return;
    int src = ei[e];
    int dst = ei[E + e];
    int h   = lane >> 3;
    float w = EW[(size_t)e * HH + h];
    float z = Z[(size_t)dst * HH + h];
    float alpha = w / (z + 1e-16f);
    float4 hv = *reinterpret_cast<const float4*>(hsrc + (size_t)src * HD + lane * 4);
    float4 m  = make_float4(hv.x * alpha, hv.y * alpha, hv.z * alpha, hv.w * alpha);
    atomicAdd(reinterpret_cast<float4*>(acc + (size_t)dst * HD + lane * 4), m);
}

// y = maybe_leaky(y + b1 [+ b2])
__global__ void bias_act_kernel(float* __restrict__ y,
                                const float* __restrict__ b1,
                                const float* __restrict__ b2,
                                int total, float slope, int do_act)
{
    int i = blockIdx.x * blockDim.x + threadIdx.x;
    if (i >= total) return;
    int j = i & (HD - 1);
    float v = y[i] + b1[j];
    if (b2) v += b2[j];
    if (do_act) v = fmaxf(v, slope * v);
    y[i] = v;
}

// ---------------- tf32 tensor-core GEMM ----------------
// C[M,Nc] = A[M,128] @ B[128,Nc] (+bias), K fixed = 128.
// Block tile 128x128x32; 8 warps = 2(M) x 4(N); warp tile 64x32.
// SMEM holds mma fragments directly (fragment-major), so the inner loop is
// conflict-free LDS.128/LDS.64 + mma.m16n8k8.tf32.

__device__ __forceinline__ uint32_t f2tf32(float x) {
    uint32_t r; asm("cvt.rna.tf32.f32 %0, %1;" : "=r"(r) : "f"(x)); return r;
}

__device__ __forceinline__ void mma_tf32(float& c0, float& c1, float& c2, float& c3,
                                         uint32_t a0, uint32_t a1, uint32_t a2, uint32_t a3,
                                         uint32_t b0, uint32_t b1)
{
    asm volatile(
        "mma.sync.aligned.m16n8k8.row.col.f32.tf32.tf32.f32 "
        "{%0,%1,%2,%3}, {%4,%5,%6,%7}, {%8,%9}, {%0,%1,%2,%3};"
        : "+f"(c0), "+f"(c1), "+f"(c2), "+f"(c3)
        : "r"(a0), "r"(a1), "r"(a2), "r"(a3), "r"(b0), "r"(b1));
}

template <bool NC_ALIGNED>
__global__ void __launch_bounds__(256) gemm_tf32_kernel(
    const float* __restrict__ A, const float* __restrict__ B,
    float* __restrict__ C, int M, int Nc, const float* __restrict__ bias)
{
    // Afrag[k8][m16][lane][4 regs], Bfrag[k8][n8][lane][2 regs]
    __shared__ uint32_t Af[4 * 8 * 32 * 4];    // 16 KB
    __shared__ uint32_t Bf[4 * 16 * 32 * 2];   // 16 KB

    const int tid  = threadIdx.x;
    const int lane = tid & 31;
    const int w    = tid >> 5;
    const int wm   = w & 1;                    // warp row (0..1) -> 64 rows
    const int wn   = w >> 1;                   // warp col (0..3) -> 32 cols
    const int m0   = blockIdx.x * 128;
    const int n0   = blockIdx.y * 128;

    float acc[4][4][4];
    #pragma unroll
    for (int i = 0; i < 4; i++)
        #pragma unroll
        for (int j = 0; j < 4; j++)
            #pragma unroll
            for (int q = 0; q < 4; q++) acc[i][j][q] = 0.f;

    for (int k0 = 0; k0 < 128; k0 += 32) {
        // ---- stage A tile (128 rows x 32 k) into fragment layout ----
        #pragma unroll
        for (int it = 0; it < 4; it++) {
            int idx = tid + it * 256;          // 0..1023 float4s
            int r   = idx >> 3;                // row 0..127
            int kc  = idx & 7;                 // which float4 in the 32-k strip
            float4 v = make_float4(0.f, 0.f, 0.f, 0.f);
            int gm = m0 + r;
            if (gm < M)
                v = *reinterpret_cast<const float4*>(A + (size_t)gm * 128 + k0 + kc * 4);
            int k8    = kc >> 1;
            int m16   = r >> 4;
            int reg   = ((kc & 1) << 1) | ((r >> 3) & 1);
            int lbase = (r & 7) << 2;
            uint32_t* dst = &Af[((k8 * 8 + m16) << 7) + reg];
            dst[(lbase + 0) * 4] = f2tf32(v.x);
            dst[(lbase + 1) * 4] = f2tf32(v.y);
            dst[(lbase + 2) * 4] = f2tf32(v.z);
            dst[(lbase + 3) * 4] = f2tf32(v.w);
        }
        // ---- stage B tile (32 k-rows x 128 cols) ----
        #pragma unroll
        for (int it = 0; it < 4; it++) {
            int idx = tid + it * 256;
            int kr  = idx >> 5;                // 0..31
            int cq  = idx & 31;                // which float4 of the 128 cols
            int gk  = k0 + kr;
            int gc  = n0 + cq * 4;
            float4 v = make_float4(0.f, 0.f, 0.f, 0.f);
            if (NC_ALIGNED) {
                v = *reinterpret_cast<const float4*>(B + (size_t)gk * Nc + gc);
            } else {
                if (gc + 0 < Nc) v.x = B[(size_t)gk * Nc + gc + 0];
                if (gc + 1 < Nc) v.y = B[(size_t)gk * Nc + gc + 1];
                if (gc + 2 < Nc) v.z = B[(size_t)gk * Nc + gc + 2];
                if (gc + 3 < Nc) v.w = B[(size_t)gk * Nc + gc + 3];
            }
            int k8   = kr >> 3;
            int reg  = (kr >> 2) & 1;
            int n8   = cq >> 1;
            int lsub = (cq & 1) << 2;          // col-in-8 base (0 or 4)
            int tig  = kr & 3;
            uint32_t* dst = &Bf[((k8 * 16 + n8) << 6) + reg];
            dst[((lsub + 0) * 4 + tig) * 2] = f2tf32(v.x);
            dst[((lsub + 1) * 4 + tig) * 2] = f2tf32(v.y);
            dst[((lsub + 2) * 4 + tig) * 2] = f2tf32(v.z);
            dst[((lsub + 3) * 4 + tig) * 2] = f2tf32(v.w);
        }
        __syncthreads();

        // ---- compute: 4 k8 steps ----
        #pragma unroll
        for (int k8 = 0; k8 < 4; k8++) {
            uint32_t a[4][4];
            uint32_t b[4][2];
            #pragma unroll
            for (int i = 0; i < 4; i++) {
                uint4 t = *reinterpret_cast<uint4*>(
                    &Af[((k8 * 8 + wm * 4 + i) << 7) + (lane << 2)]);
                a[i][0] = t.x; a[i][1] = t.y; a[i][2] = t.z; a[i][3] = t.w;
            }
            #pragma unroll
            for (int j = 0; j < 4; j++) {
                uint2 t = *reinterpret_cast<uint2*>(
                    &Bf[((k8 * 16 + wn * 4 + j) << 6) + (lane << 1)]);
                b[j][0] = t.x; b[j][1] = t.y;
            }
            #pragma unroll
            for (int i = 0; i < 4; i++)
                #pragma unroll
                for (int j = 0; j < 4; j++)
                    mma_tf32(acc[i][j][0], acc[i][j][1], acc[i][j][2], acc[i][j][3],
                             a[i][0], a[i][1], a[i][2], a[i][3], b[j][0], b[j][1]);
        }
        __syncthreads();
    }

    // ---- epilogue ----
    const int gID = lane >> 2;
    const int tig = lane & 3;
    #pragma unroll
    for (int i = 0; i < 4; i++) {
        int row0 = m0 + wm * 64 + i * 16 + gID;
        #pragma unroll
        for (int j = 0; j < 4; j++) {
            int col = n0 + wn * 32 + j * 8 + tig * 2;
            float bx = 0.f, by = 0.f;
            if (bias) {
                if (col < Nc)     bx = bias[col];
                if (col + 1 < Nc) by = bias[col + 1];
            }
            if (NC_ALIGNED) {
                if (row0 < M) {
                    float2 o = make_float2(acc[i][j][0] + bx, acc[i][j][1] + by);
                    *reinterpret_cast<float2*>(C + (size_t)row0 * Nc + col) = o;
                }
                if (row0 + 8 < M) {
                    float2 o = make_float2(acc[i][j][2] + bx, acc[i][j][3] + by);
                    *reinterpret_cast<float2*>(C + (size_t)(row0 + 8) * Nc + col) = o;
                }
            } else {
                if (row0 < M) {
                    if (col < Nc)     C[(size_t)row0 * Nc + col]     = acc[i][j][0] + bx;
                    if (col + 1 < Nc) C[(size_t)row0 * Nc + col + 1] = acc[i][j][1] + by;
                }
                if (row0 + 8 < M) {
                    if (col < Nc)     C[(size_t)(row0 + 8) * Nc + col]     = acc[i][j][2] + bx;
                    if (col + 1 < Nc) C[(size_t)(row0 + 8) * Nc + col + 1] = acc[i][j][3] + by;
                }
            }
        }
    }
}

// ---------------- host launch ----------------
extern "C" void kernel_launch(void* const* d_in, const int* in_sizes, int n_in,
                              void* d_out, int out_size)
{
    const float* xs[2]   = {nullptr, nullptr}; int nx = 0;
    const int*   eis[3]  = {nullptr, nullptr, nullptr}; int ne = 0;
    const float* Ws[6]   = {}; int nw = 0;
    const float* attb[18]= {}; int na = 0;
    const float* linW = nullptr;
    const float* linb = nullptr;

    for (int i = 0; i < n_in; i++) {
        int s = in_sizes[i];
        if      (s == NN * DIN   && nx < 2)  xs[nx++]   = (const float*)d_in[i];
        else if (s == 2 * EE     && ne < 3)  eis[ne++]  = (const int*)d_in[i];
        else if (s == DIN * HD   && nw < 6)  Ws[nw++]   = (const float*)d_in[i];
        else if (s == HD         && na < 18) attb[na++] = (const float*)d_in[i];
        else if (s == HD * NOUT)             linW       = (const float*)d_in[i];
        else if (s == NOUT)                  linb       = (const float*)d_in[i];
    }
    if (nx != 2 || ne != 3 || nw != 6 || na != 18 || !linW || !linb) return;

    float *pH1, *pXP1, *pXA1, *pXP2, *pP, *pZ, *pEW, *pV;
    cudaGetSymbolAddress((void**)&pH1,  g_H1);
    cudaGetSymbolAddress((void**)&pXP1, g_XP1);
    cudaGetSymbolAddress((void**)&pXA1, g_XA1);
    cudaGetSymbolAddress((void**)&pXP2, g_XP2);
    cudaGetSymbolAddress((void**)&pP,   g_P);
    cudaGetSymbolAddress((void**)&pZ,   g_Z);
    cudaGetSymbolAddress((void**)&pEW,  g_EW);
    cudaGetSymbolAddress((void**)&pV,   g_V);

    float* AS_c  = pP + 0 * (size_t)NN * HH;
    float* AD_c  = pP + 1 * (size_t)NN * HH;
    float* AD_w  = pP + 2 * (size_t)NN * HH;
    float* AS_wb = pP + 3 * (size_t)NN * HH;
    float* AS_w  = pP + 4 * (size_t)NN * HH;
    float* AD_wb = pP + 5 * (size_t)NN * HH;
    float* Z0 = pZ;
    float* Z1 = pZ + (size_t)NN * HH;
    float* Z2 = pZ + 2 * (size_t)NN * HH;

    const size_t featBytes = (size_t)NN * HD * sizeof(float);
    const int total = NN * HD;
    const dim3 ggrid((NN + 127) / 128, 1);

    // ================= layer 0 =================
    cudaMemsetAsync(pXP1, 0, featBytes);
    cudaMemsetAsync(pXA1, 0, featBytes);
    cudaMemsetAsync(pZ, 0, 3 * (size_t)NN * HH * sizeof(float));

    prep_v_kernel<<<1, 128>>>(Ws[0], attb[0], pV + 0);      // as0_c
    prep_v_kernel<<<1, 128>>>(Ws[0], attb[1], pV + 512);    // ad0_c
    // launch #5 -> profiled by ncu: the first tf32 GEMM
    gemm_tf32_kernel<true><<<ggrid, 256>>>(xs[0], Ws[0], pH1, NN, HD, nullptr);

    prep_v_kernel<<<1, 128>>>(Ws[1], attb[4], pV + 1024);   // ad0_w
    prep_v_kernel<<<1, 128>>>(Ws[2], attb[6], pV + 1536);   // as0_wb
    prep_v_kernel<<<1, 128>>>(Ws[1], attb[3], pV + 2048);   // as0_w
    prep_v_kernel<<<1, 128>>>(Ws[2], attb[7], pV + 2560);   // ad0_wb

    proj_multi_kernel<4><<<1024, 256>>>(xs[0], pV,        AS_c, AD_c, AD_w, AS_wb, NN);
    proj_multi_kernel<2><<<1024, 256>>>(xs[1], pV + 2048, AS_w, AD_wb, nullptr, nullptr, NN);

    // cites: paper -> paper
    edge_logits_kernel <<<(EE + 255) / 256, 256>>>(eis[0], AS_c, AD_c, pEW, Z0, EE);
    edge_scatter_kernel<<<(EE + 7) / 8,     256>>>(eis[0], pH1, Z0, pEW, pXP1, EE);
    // writes: author -> paper
    gemm_tf32_kernel<true><<<ggrid, 256>>>(xs[1], Ws[1], pH1, NN, HD, nullptr);
    edge_logits_kernel <<<(EE + 255) / 256, 256>>>(eis[1], AS_w, AD_w, pEW, Z1, EE);
    edge_scatter_kernel<<<(EE + 7) / 8,     256>>>(eis[1], pH1, Z1, pEW, pXP1, EE);
    // written_by: paper -> author
    gemm_tf32_kernel<true><<<ggrid, 256>>>(xs[0], Ws[2], pH1, NN, HD, nullptr);
    edge_logits_kernel <<<(EE + 255) / 256, 256>>>(eis[2], AS_wb, AD_wb, pEW, Z2, EE);
    edge_scatter_kernel<<<(EE + 7) / 8,     256>>>(eis[2], pH1, Z2, pEW, pXA1, EE);

    bias_act_kernel<<<(total + 255) / 256, 256>>>(pXP1, attb[2], attb[5], total, 0.01f, 1);
    bias_act_kernel<<<(total + 255) / 256, 256>>>(pXA1, attb[8], nullptr, total, 0.01f, 1);

    // ================= layer 1 (author output dead) =================
    cudaMemsetAsync(pXP2, 0, featBytes);
    cudaMemsetAsync(pZ, 0, 2 * (size_t)NN * HH * sizeof(float));

    prep_v_kernel<<<1, 128>>>(Ws[3], attb[9],  pV + 0);     // as1_c
    prep_v_kernel<<<1, 128>>>(Ws[3], attb[10], pV + 512);   // ad1_c
    prep_v_kernel<<<1, 128>>>(Ws[4], attb[13], pV + 1024);  // ad1_w
    prep_v_kernel<<<1, 128>>>(Ws[4], attb[12], pV + 2048);  // as1_w

    proj_multi_kernel<3><<<1024, 256>>>(pXP1, pV,        AS_c, AD_c, AD_w, nullptr, NN);
    proj_multi_kernel<1><<<1024, 256>>>(pXA1, pV + 2048, AS_w, nullptr, nullptr, nullptr, NN);

    // cites
    gemm_tf32_kernel<true><<<ggrid, 256>>>(pXP1, Ws[3], pH1, NN, HD, nullptr);
    edge_logits_kernel <<<(EE + 255) / 256, 256>>>(eis[0], AS_c, AD_c, pEW, Z0, EE);
    edge_scatter_kernel<<<(EE + 7) / 8,     256>>>(eis[0], pH1, Z0, pEW, pXP2, EE);
    // writes
    gemm_tf32_kernel<true><<<ggrid, 256>>>(pXA1, Ws[4], pH1, NN, HD, nullptr);
    edge_logits_kernel <<<(EE + 255) / 256, 256>>>(eis[1], AS_w, AD_w, pEW, Z1, EE);
    edge_scatter_kernel<<<(EE + 7) / 8,     256>>>(eis[1], pH1, Z1, pEW, pXP2, EE);

    bias_act_kernel<<<(total + 255) / 256, 256>>>(pXP2, attb[11], attb[14], total, 0.f, 0);

    // classifier: out[N,349] = xp2 @ lin_W + lin_b
    gemm_tf32_kernel<false><<<dim3((NN + 127) / 128, (NOUT + 127) / 128), 256>>>(
        pXP2, linW, (float*)d_out, NN, NOUT, linb);
}